// round 13
// baseline (speedup 1.0000x reference)
#include <cuda_runtime.h>
#include <math.h>
#include <stdint.h>

#define L_  512
#define B_  8
#define N_  32
#define D_  256
#define GH_ 128
#define AH_ 64

// Packed fp32x2 ops (sm_103a; PTX-only, ptxas never auto-generates)
#define FMA_F32X2(d, a, b, c) \
    asm("fma.rn.f32x2 %0, %1, %2, %3;" : "=l"(d) : "l"(a), "l"(b), "l"(c))
#define PACK_F32X2(out, lo, hi) \
    asm("mov.b64 %0, {%1, %2};" : "=l"(out) : "f"(lo), "f"(hi))
#define UNPACK_F32X2(lo, hi, in) \
    asm("mov.b64 {%0, %1}, %2;" : "=f"(lo), "=f"(hi) : "l"(in))

// Pre-transposed weights: [k][j] layouts for conflict-free LDS.128 in the GEMMs.
__device__ float g_gw1T[2 * D_ * GH_];   // [512][128]
__device__ float g_aw1T[D_ * AH_];       // [256][64]

__global__ void transpose_weights_kernel(const float* __restrict__ gw1,
                                         const float* __restrict__ aw1) {
    int i = blockIdx.x * blockDim.x + threadIdx.x;
    if (i < 2 * D_ * GH_) {
        int j = i / (2 * D_);
        int k = i % (2 * D_);
        g_gw1T[k * GH_ + j] = gw1[i];
    }
    if (i < D_ * AH_) {
        int j = i / D_;
        int k = i % D_;
        g_aw1T[k * AH_ + j] = aw1[i];
    }
}

// Fully fused, 1 (l,b) group per CTA, 256 threads, 2 CTAs/SM.
__global__ __launch_bounds__(256, 2)
void fused_kernel(const float* __restrict__ vert,
                  const float* __restrict__ horiz,
                  const int* __restrict__ mask,    // [B][N][L] bool as int32
                  const float* __restrict__ gb1,
                  const float* __restrict__ gw2,
                  const float* __restrict__ gb2,
                  const float* __restrict__ ab1,
                  const float* __restrict__ aw2,
                  const float* __restrict__ ab2,
                  float* __restrict__ out_fused,   // [L*B][D]
                  float* __restrict__ out_pm,      // [L*B*N][D]
                  float* __restrict__ out_attn)    // [B][L][N]
{
    extern __shared__ float smem[];
    float* vert_s  = smem;                     // 32*256 (becomes per_msg in place)
    float* horiz_s = vert_s  + N_ * D_;        // 32*256
    float* wbuf0   = horiz_s + N_ * D_;        // 4096 floats
    float* wbuf1   = wbuf0   + 4096;           // 4096 floats
    float* gate_s  = wbuf1   + 4096;           // 32
    float* red_s   = gate_s  + N_;             // 32
    float* attn_s  = red_s   + N_;             // 32

    const int bid  = blockIdx.x;               // = l*B + b
    const int l    = bid / B_;
    const int b    = bid % B_;
    const int tid  = threadIdx.x;
    const int lane = tid & 31;
    const int warp = tid >> 5;

    // ---- Phase 1: load vert/horiz tiles (coalesced float4) ----
    {
        const float4* vsrc = (const float4*)(vert  + (size_t)bid * N_ * D_);
        const float4* hsrc = (const float4*)(horiz + (size_t)bid * N_ * D_);
        float4* vdst = (float4*)vert_s;
        float4* hdst = (float4*)horiz_s;
        #pragma unroll
        for (int i = tid; i < N_ * D_ / 4; i += 256) {
            vdst[i] = vsrc[i];
            hdst[i] = hsrc[i];
        }
    }

    // ---- Phase 2: gate GEMM  h[32][128] = comb[32][512] @ gw1^T  (FFMA2) ----
    // thread tile: 4 msgs x 4 outs (= 2 f32x2 pairs). tm = warp (8x4 rows), tn = lane.
    const int tn = lane;
    const int tm = warp;
    unsigned long long accp[4][2];
    #pragma unroll
    for (int i = 0; i < 4; ++i) { accp[i][0] = 0ull; accp[i][1] = 0ull; }

    const float4* wsrc = (const float4*)g_gw1T;   // 16384 float4, tile = 1024 f4
    float4 pre[4];
    #pragma unroll
    for (int u = 0; u < 4; ++u) pre[u] = wsrc[tid + 256 * u];   // tile 0
    __syncthreads();                                            // phase-1 tiles visible
    {
        float4* dst = (float4*)wbuf0;
        #pragma unroll
        for (int u = 0; u < 4; ++u) dst[tid + 256 * u] = pre[u];
    }
    __syncthreads();

    for (int kt = 0; kt < 16; ++kt) {
        const float* wcur = (kt & 1) ? wbuf1 : wbuf0;
        float*       wnxt = (kt & 1) ? wbuf0 : wbuf1;
        if (kt < 15) {
            #pragma unroll
            for (int u = 0; u < 4; ++u) pre[u] = wsrc[(kt + 1) * 1024 + tid + 256 * u];
        }
        const float* comb = (kt < 8) ? (vert_s + kt * 32) : (horiz_s + (kt - 8) * 32);
        #pragma unroll
        for (int kk4 = 0; kk4 < 8; ++kk4) {
            float4 cv[4];
            #pragma unroll
            for (int mi = 0; mi < 4; ++mi)
                cv[mi] = *(const float4*)(comb + (tm * 4 + mi) * D_ + kk4 * 4);
            const float* cvf = (const float*)cv;
            #pragma unroll
            for (int kk = 0; kk < 4; ++kk) {
                const ulonglong2 wp =
                    *(const ulonglong2*)(wcur + (kk4 * 4 + kk) * GH_ + tn * 4);
                #pragma unroll
                for (int mi = 0; mi < 4; ++mi) {
                    float c = cvf[mi * 4 + kk];
                    unsigned long long cb;
                    PACK_F32X2(cb, c, c);
                    FMA_F32X2(accp[mi][0], cb, wp.x, accp[mi][0]);
                    FMA_F32X2(accp[mi][1], cb, wp.y, accp[mi][1]);
                }
            }
        }
        if (kt < 15) {
            float4* dst = (float4*)wnxt;
            #pragma unroll
            for (int u = 0; u < 4; ++u) dst[tid + 256 * u] = pre[u];
        }
        __syncthreads();
    }

    // ---- Phase 3: bias+relu in registers, gate dot via shfl ----
    {
        float4 bias = *(const float4*)(gb1 + tn * 4);
        float4 w2v  = *(const float4*)(gw2 + tn * 4);
        float  g2b  = gb2[0];
        #pragma unroll
        for (int mi = 0; mi < 4; ++mi) {
            float a0, a1, a2, a3;
            UNPACK_F32X2(a0, a1, accp[mi][0]);
            UNPACK_F32X2(a2, a3, accp[mi][1]);
            float h0 = fmaxf(a0 + bias.x, 0.f);
            float h1 = fmaxf(a1 + bias.y, 0.f);
            float h2 = fmaxf(a2 + bias.z, 0.f);
            float h3 = fmaxf(a3 + bias.w, 0.f);
            float p = h0 * w2v.x + h1 * w2v.y + h2 * w2v.z + h3 * w2v.w;
            #pragma unroll
            for (int o = 16; o; o >>= 1) p += __shfl_xor_sync(0xffffffffu, p, o);
            if (lane == 0) gate_s[tm * 4 + mi] = 1.f / (1.f + __expf(-(p + g2b)));
        }
    }
    __syncthreads();

    // ---- Phase 4: blend -> per_msg (in place) + global per_msg ----
    {
        float* pm_out = out_pm + (size_t)bid * N_ * D_;
        #pragma unroll 4
        for (int m = 0; m < N_; ++m) {
            float g = gate_s[m];
            float pm = g * vert_s[m * D_ + tid] + (1.f - g) * horiz_s[m * D_ + tid];
            vert_s[m * D_ + tid] = pm;
            pm_out[m * D_ + tid] = pm;
        }
    }
    __syncthreads();

    // ---- Phase 5: scorer GEMM  a[32][64] = pm[32][256] @ aw1^T  (FFMA2) ----
    // thread tile 2m x 4j: tm2 = tid>>4 (16 groups of 2), tn2 = tid&15 (16 groups of 4)
    const int tn2 = tid & 15;
    const int tm2 = tid >> 4;
    unsigned long long accp2[2][2];
    #pragma unroll
    for (int i = 0; i < 2; ++i) { accp2[i][0] = 0ull; accp2[i][1] = 0ull; }

    const float4* asrc = (const float4*)g_aw1T;   // 4096 f4, tile = 1024 f4
    #pragma unroll
    for (int u = 0; u < 4; ++u) pre[u] = asrc[tid + 256 * u];
    {
        float4* dst = (float4*)wbuf0;
        #pragma unroll
        for (int u = 0; u < 4; ++u) dst[tid + 256 * u] = pre[u];
    }
    __syncthreads();

    for (int kt = 0; kt < 4; ++kt) {
        const float* wcur = (kt & 1) ? wbuf1 : wbuf0;
        float*       wnxt = (kt & 1) ? wbuf0 : wbuf1;
        if (kt < 3) {
            #pragma unroll
            for (int u = 0; u < 4; ++u) pre[u] = asrc[(kt + 1) * 1024 + tid + 256 * u];
        }
        #pragma unroll
        for (int kk4 = 0; kk4 < 16; ++kk4) {
            float4 cv[2];
            #pragma unroll
            for (int mi = 0; mi < 2; ++mi)
                cv[mi] = *(const float4*)(vert_s + (tm2 * 2 + mi) * D_ + kt * 64 + kk4 * 4);
            const float* cvf = (const float*)cv;
            #pragma unroll
            for (int kk = 0; kk < 4; ++kk) {
                const ulonglong2 wp =
                    *(const ulonglong2*)(wcur + (kk4 * 4 + kk) * AH_ + tn2 * 4);
                #pragma unroll
                for (int mi = 0; mi < 2; ++mi) {
                    float c = cvf[mi * 4 + kk];
                    unsigned long long cb;
                    PACK_F32X2(cb, c, c);
                    FMA_F32X2(accp2[mi][0], cb, wp.x, accp2[mi][0]);
                    FMA_F32X2(accp2[mi][1], cb, wp.y, accp2[mi][1]);
                }
            }
        }
        if (kt < 3) {
            float4* dst = (float4*)wnxt;
            #pragma unroll
            for (int u = 0; u < 4; ++u) dst[tid + 256 * u] = pre[u];
        }
        __syncthreads();
    }

    // tanh + bias -> a_s (use wbuf0: free after last sync)
    float* a_s = wbuf0;   // [32][64]
    {
        float4 bias = *(const float4*)(ab1 + tn2 * 4);
        #pragma unroll
        for (int mi = 0; mi < 2; ++mi) {
            float a0, a1, a2, a3;
            UNPACK_F32X2(a0, a1, accp2[mi][0]);
            UNPACK_F32X2(a2, a3, accp2[mi][1]);
            float4 v;
            v.x = tanhf(a0 + bias.x);
            v.y = tanhf(a1 + bias.y);
            v.z = tanhf(a2 + bias.z);
            v.w = tanhf(a3 + bias.w);
            *(float4*)(a_s + (tm2 * 2 + mi) * AH_ + tn2 * 4) = v;
        }
    }
    __syncthreads();

    // ---- Phase 6: logits + mask (8 warps x 4 rows) ----
    {
        #pragma unroll
        for (int mi = 0; mi < 4; ++mi) {
            int m = warp * 4 + mi;                  // 0..31
            float d = a_s[m * AH_ + lane] * aw2[lane]
                    + a_s[m * AH_ + lane + 32] * aw2[lane + 32];
            #pragma unroll
            for (int o = 16; o; o >>= 1) d += __shfl_xor_sync(0xffffffffu, d, o);
            if (lane == 0) {
                bool valid = mask[((size_t)b * N_ + m) * L_ + l] != 0;
                red_s[m] = valid ? (d + ab2[0]) : -INFINITY;
            }
        }
    }
    __syncthreads();

    // ---- Phase 7: masked softmax over N=32 (warp 0) ----
    if (warp == 0) {
        float lg = red_s[lane];
        float mx = lg;
        #pragma unroll
        for (int o = 16; o; o >>= 1) mx = fmaxf(mx, __shfl_xor_sync(0xffffffffu, mx, o));
        float e = (mx == -INFINITY || lg == -INFINITY) ? 0.f : __expf(lg - mx);
        float s = e;
        #pragma unroll
        for (int o = 16; o; o >>= 1) s += __shfl_xor_sync(0xffffffffu, s, o);
        float a = (s > 0.f) ? (e / s) : 0.f;    // fully-masked row -> 0 (nan_to_num)
        attn_s[lane] = a;
        out_attn[(size_t)b * L_ * N_ + (size_t)l * N_ + lane] = a;
    }
    __syncthreads();

    // ---- Phase 8: fused[l,b,d] = sum_n attn[n] * per_msg[n,d] ----
    {
        float facc = 0.f;
        #pragma unroll 8
        for (int n = 0; n < N_; ++n)
            facc += attn_s[n] * vert_s[n * D_ + tid];
        out_fused[(size_t)bid * D_ + tid] = facc;
    }
}

extern "C" void kernel_launch(void* const* d_in, const int* in_sizes, int n_in,
                              void* d_out, int out_size) {
    const float* vert  = (const float*)d_in[0];
    const float* horiz = (const float*)d_in[1];
    const int*   mask  = (const int*)d_in[2];   // bool materialized as int32
    const float* gw1 = (const float*)d_in[3];
    const float* gb1 = (const float*)d_in[4];
    const float* gw2 = (const float*)d_in[5];
    const float* gb2 = (const float*)d_in[6];
    const float* aw1 = (const float*)d_in[7];
    const float* ab1 = (const float*)d_in[8];
    const float* aw2 = (const float*)d_in[9];
    const float* ab2 = (const float*)d_in[10];

    float* out = (float*)d_out;
    float* out_fused = out;                                   // L*B*D
    float* out_pm    = out + (size_t)L_ * B_ * D_;            // L*B*N*D
    float* out_attn  = out_pm + (size_t)L_ * B_ * N_ * D_;    // B*L*N

    const size_t smem_bytes = (size_t)(N_ * D_ * 2 + 4096 * 2 + 3 * N_) * sizeof(float);

    cudaFuncSetAttribute(fused_kernel,
                         cudaFuncAttributeMaxDynamicSharedMemorySize,
                         (int)smem_bytes);

    transpose_weights_kernel<<<(2 * D_ * GH_ + 255) / 256, 256>>>(gw1, aw1);
    fused_kernel<<<L_ * B_, 256, smem_bytes>>>(
        vert, horiz, mask, gb1, gw2, gb2, ab1, aw2, ab2,
        out_fused, out_pm, out_attn);
}

// round 15
// speedup vs baseline: 1.2708x; 1.2708x over previous
#include <cuda_runtime.h>
#include <math.h>
#include <stdint.h>

#define L_  512
#define B_  8
#define N_  32
#define D_  256
#define GH_ 128
#define AH_ 64
#define M2_ 64

// Packed fp32x2 ops (sm_103a; PTX-only)
#define FMA_F32X2(d, a, b, c) \
    asm("fma.rn.f32x2 %0, %1, %2, %3;" : "=l"(d) : "l"(a), "l"(b), "l"(c))
#define ADD_F32X2(d, a, b) \
    asm("add.rn.f32x2 %0, %1, %2;" : "=l"(d) : "l"(a), "l"(b))
#define PACK_F32X2(out, lo, hi) \
    asm("mov.b64 %0, {%1, %2};" : "=l"(out) : "f"(lo), "f"(hi))
#define UNPACK_F32X2(lo, hi, in) \
    asm("mov.b64 {%0, %1}, %2;" : "=f"(lo), "=f"(hi) : "l"(in))

#define CP_ASYNC16(saddr, gptr) \
    asm volatile("cp.async.cg.shared.global [%0], [%1], 16;" :: "r"(saddr), "l"(gptr))
#define CP_COMMIT()  asm volatile("cp.async.commit_group;")
#define CP_WAIT0()   asm volatile("cp.async.wait_group 0;" ::: "memory")
#define BARH(id)     asm volatile("bar.sync %0, 256;" :: "r"(id) : "memory")

// Pre-transposed weights: [k][j] layouts for conflict-free LDS.128.
__device__ float g_gw1T[2 * D_ * GH_];   // [512][128]
__device__ float g_aw1T[D_ * AH_];       // [256][64]

__global__ void transpose_weights_kernel(const float* __restrict__ gw1,
                                         const float* __restrict__ aw1) {
    int i = blockIdx.x * blockDim.x + threadIdx.x;
    if (i < 2 * D_ * GH_) {
        int j = i / (2 * D_);
        int k = i % (2 * D_);
        g_gw1T[k * GH_ + j] = gw1[i];
    }
    if (i < D_ * AH_) {
        int j = i / D_;
        int k = i % D_;
        g_aw1T[k * AH_ + j] = aw1[i];
    }
}

// 2 (l,b) groups per CTA, 512 threads, split-K across two 256-thread halves.
__global__ __launch_bounds__(512, 1)
void fused_kernel(const float* __restrict__ vert,
                  const float* __restrict__ horiz,
                  const int* __restrict__ mask,    // [B][N][L] bool as int32
                  const float* __restrict__ gb1,
                  const float* __restrict__ gw2,
                  const float* __restrict__ gb2,
                  const float* __restrict__ ab1,
                  const float* __restrict__ aw2,
                  const float* __restrict__ ab2,
                  float* __restrict__ out_fused,   // [L*B][D]
                  float* __restrict__ out_pm,      // [L*B*N][D]
                  float* __restrict__ out_attn)    // [B][L][N]
{
    extern __shared__ float smem[];
    float* vert_s  = smem;                     // 64*256 (becomes per_msg)
    float* horiz_s = vert_s  + M2_ * D_;       // 64*256
    float* warea   = horiz_s + M2_ * D_;       // 4*4096 floats (2 bufs per half)
    float* gate_s  = warea   + 4 * 4096;       // 64
    float* red_s   = gate_s  + M2_;            // 64
    float* attn_s  = red_s   + M2_;            // 64

    const int bid0 = blockIdx.x * 2;
    const int tid  = threadIdx.x;
    const int lane = tid & 31;
    const int warp = tid >> 5;
    const int half = tid >> 8;                 // 0 or 1
    const int htid = tid & 255;
    const int hwarp= htid >> 5;

    float* wb0 = warea + half * 8192;          // this half's double buffer
    float* wb1 = wb0 + 4096;
    float* redg = warea + 8192;                // gate partials: 64*128 (= half1's bufs)
    float* reds = warea + 8192;                // scorer partials: 64*64 (half1's wb0)
    float* a_s  = warea;                       // tanh acts: 64*64 (half0's wb0)

    const uint32_t wb0a = (uint32_t)__cvta_generic_to_shared(wb0);
    const uint32_t wb1a = (uint32_t)__cvta_generic_to_shared(wb1);

    // ---- Phase 1: load 2 groups of vert/horiz (512 threads) ----
    {
        const float4* vsrc = (const float4*)(vert  + (size_t)bid0 * N_ * D_);
        const float4* hsrc = (const float4*)(horiz + (size_t)bid0 * N_ * D_);
        float4* vdst = (float4*)vert_s;
        float4* hdst = (float4*)horiz_s;
        #pragma unroll
        for (int i = tid; i < M2_ * D_ / 4; i += 512) {
            vdst[i] = vsrc[i];
            hdst[i] = hsrc[i];
        }
    }

    // ---- Phase 2: gate GEMM (split-K). Each half: 8 ktiles of 32 on its own input. ----
    const int tn = lane;       // 32 j-groups of 4
    const int tm = hwarp;      // 8 m-groups of 8
    unsigned long long accp[8][2];
    #pragma unroll
    for (int i = 0; i < 8; ++i) { accp[i][0] = 0ull; accp[i][1] = 0ull; }

    const float4* wsrc = (const float4*)(g_gw1T + half * 8 * 4096);  // this half's 8 tiles
    const float* comb_base = half ? horiz_s : vert_s;

    // preload tile 0 via cp.async
    #pragma unroll
    for (int u = 0; u < 4; ++u)
        CP_ASYNC16(wb0a + (htid + 256 * u) * 16, wsrc + htid + 256 * u);
    CP_COMMIT();
    CP_WAIT0();
    __syncthreads();    // phase-1 tiles + everyone's tile 0 visible

    for (int kt = 0; kt < 8; ++kt) {
        const float* wcur = (kt & 1) ? wb1 : wb0;
        if (kt < 7) {
            uint32_t nxt = (kt & 1) ? wb0a : wb1a;
            #pragma unroll
            for (int u = 0; u < 4; ++u)
                CP_ASYNC16(nxt + (htid + 256 * u) * 16, wsrc + (kt + 1) * 1024 + htid + 256 * u);
            CP_COMMIT();
        }
        const float* comb = comb_base + kt * 32;
        #pragma unroll
        for (int kk4 = 0; kk4 < 8; ++kk4) {
            float4 cv[8];
            #pragma unroll
            for (int mi = 0; mi < 8; ++mi)
                cv[mi] = *(const float4*)(comb + (tm * 8 + mi) * D_ + kk4 * 4);
            const float* cvf = (const float*)cv;
            #pragma unroll
            for (int kk = 0; kk < 4; ++kk) {
                const ulonglong2 wp =
                    *(const ulonglong2*)(wcur + (kk4 * 4 + kk) * GH_ + tn * 4);
                #pragma unroll
                for (int mi = 0; mi < 8; ++mi) {
                    float c = cvf[mi * 4 + kk];
                    unsigned long long cb;
                    PACK_F32X2(cb, c, c);
                    FMA_F32X2(accp[mi][0], cb, wp.x, accp[mi][0]);
                    FMA_F32X2(accp[mi][1], cb, wp.y, accp[mi][1]);
                }
            }
        }
        if (kt < 7) {
            CP_WAIT0();
            BARH(1 + half);
        }
    }
    BARH(1 + half);   // half-scope: all compute done before partial dump

    // half 1 dumps partials into its own (dead) weight buffers
    if (half == 1) {
        #pragma unroll
        for (int mi = 0; mi < 8; ++mi) {
            *(unsigned long long*)(redg + (tm * 8 + mi) * GH_ + tn * 4)     = accp[mi][0];
            *(unsigned long long*)(redg + (tm * 8 + mi) * GH_ + tn * 4 + 2) = accp[mi][1];
        }
    }
    __syncthreads();

    // ---- Phase 3 (half 0): reduce + bias + relu + gate dot + sigmoid ----
    if (half == 0) {
        float4 bias = *(const float4*)(gb1 + tn * 4);
        float4 w2v  = *(const float4*)(gw2 + tn * 4);
        float  g2b  = gb2[0];
        #pragma unroll
        for (int mi = 0; mi < 8; ++mi) {
            unsigned long long p0 = *(const unsigned long long*)(redg + (tm * 8 + mi) * GH_ + tn * 4);
            unsigned long long p1 = *(const unsigned long long*)(redg + (tm * 8 + mi) * GH_ + tn * 4 + 2);
            ADD_F32X2(p0, accp[mi][0], p0);
            ADD_F32X2(p1, accp[mi][1], p1);
            float a0, a1, a2, a3;
            UNPACK_F32X2(a0, a1, p0);
            UNPACK_F32X2(a2, a3, p1);
            float h0 = fmaxf(a0 + bias.x, 0.f);
            float h1 = fmaxf(a1 + bias.y, 0.f);
            float h2 = fmaxf(a2 + bias.z, 0.f);
            float h3 = fmaxf(a3 + bias.w, 0.f);
            float p = h0 * w2v.x + h1 * w2v.y + h2 * w2v.z + h3 * w2v.w;
            #pragma unroll
            for (int o = 16; o; o >>= 1) p += __shfl_xor_sync(0xffffffffu, p, o);
            if (lane == 0) gate_s[tm * 8 + mi] = 1.f / (1.f + __expf(-(p + g2b)));
        }
    }
    __syncthreads();

    // ---- Phase 4: blend -> per_msg (in place) + global per_msg (512 threads) ----
    {
        float* pm_out = out_pm + (size_t)bid0 * N_ * D_;
        #pragma unroll 4
        for (int m = 0; m < 32; ++m) {
            int r = half * 32 + m;
            float g = gate_s[r];
            float pm = g * vert_s[r * D_ + htid] + (1.f - g) * horiz_s[r * D_ + htid];
            vert_s[r * D_ + htid] = pm;
            pm_out[r * D_ + htid] = pm;
        }
    }
    __syncthreads();

    // ---- Phase 5: scorer GEMM (split-K). a[64][64] = pm[64][256] @ aw1^T ----
    // per half: 2 ktiles of 64 (half0: k 0..127, half1: k 128..255)
    const int tn2 = htid & 15;     // 16 j-groups of 4
    const int tm2 = htid >> 4;     // 16 m-groups of 4
    unsigned long long accp2[4][2];
    #pragma unroll
    for (int i = 0; i < 4; ++i) { accp2[i][0] = 0ull; accp2[i][1] = 0ull; }

    const float4* asrc = (const float4*)(g_aw1T + half * 2 * 4096);
    // load both tiles for this half up front
    #pragma unroll
    for (int u = 0; u < 4; ++u)
        CP_ASYNC16(wb0a + (htid + 256 * u) * 16, asrc + htid + 256 * u);
    #pragma unroll
    for (int u = 0; u < 4; ++u)
        CP_ASYNC16(wb1a + (htid + 256 * u) * 16, asrc + 1024 + htid + 256 * u);
    CP_COMMIT();
    CP_WAIT0();
    BARH(1 + half);

    #pragma unroll
    for (int ktl = 0; ktl < 2; ++ktl) {
        const float* wcur = ktl ? wb1 : wb0;
        const int k0 = (half * 2 + ktl) * 64;
        #pragma unroll
        for (int kk4 = 0; kk4 < 16; ++kk4) {
            float4 cv[4];
            #pragma unroll
            for (int mi = 0; mi < 4; ++mi)
                cv[mi] = *(const float4*)(vert_s + (tm2 * 4 + mi) * D_ + k0 + kk4 * 4);
            const float* cvf = (const float*)cv;
            #pragma unroll
            for (int kk = 0; kk < 4; ++kk) {
                const ulonglong2 wp =
                    *(const ulonglong2*)(wcur + (kk4 * 4 + kk) * AH_ + tn2 * 4);
                #pragma unroll
                for (int mi = 0; mi < 4; ++mi) {
                    float c = cvf[mi * 4 + kk];
                    unsigned long long cb;
                    PACK_F32X2(cb, c, c);
                    FMA_F32X2(accp2[mi][0], cb, wp.x, accp2[mi][0]);
                    FMA_F32X2(accp2[mi][1], cb, wp.y, accp2[mi][1]);
                }
            }
        }
    }
    BARH(1 + half);   // half-scope: compute done before partial dump

    if (half == 1) {
        #pragma unroll
        for (int mi = 0; mi < 4; ++mi) {
            *(unsigned long long*)(reds + (tm2 * 4 + mi) * AH_ + tn2 * 4)     = accp2[mi][0];
            *(unsigned long long*)(reds + (tm2 * 4 + mi) * AH_ + tn2 * 4 + 2) = accp2[mi][1];
        }
    }
    __syncthreads();

    // ---- half 0: reduce + bias + tanh -> a_s ----
    if (half == 0) {
        float4 bias = *(const float4*)(ab1 + tn2 * 4);
        #pragma unroll
        for (int mi = 0; mi < 4; ++mi) {
            unsigned long long p0 = *(const unsigned long long*)(reds + (tm2 * 4 + mi) * AH_ + tn2 * 4);
            unsigned long long p1 = *(const unsigned long long*)(reds + (tm2 * 4 + mi) * AH_ + tn2 * 4 + 2);
            ADD_F32X2(p0, accp2[mi][0], p0);
            ADD_F32X2(p1, accp2[mi][1], p1);
            float a0, a1, a2, a3;
            UNPACK_F32X2(a0, a1, p0);
            UNPACK_F32X2(a2, a3, p1);
            float4 v;
            v.x = tanhf(a0 + bias.x);
            v.y = tanhf(a1 + bias.y);
            v.z = tanhf(a2 + bias.z);
            v.w = tanhf(a3 + bias.w);
            *(float4*)(a_s + (tm2 * 4 + mi) * AH_ + tn2 * 4) = v;
        }
    }
    __syncthreads();

    // ---- Phase 6: logits + mask (16 warps x 4 rows) ----
    {
        #pragma unroll
        for (int mi = 0; mi < 4; ++mi) {
            int row = warp * 4 + mi;                 // 0..63
            float d = a_s[row * AH_ + lane] * aw2[lane]
                    + a_s[row * AH_ + lane + 32] * aw2[lane + 32];
            #pragma unroll
            for (int o = 16; o; o >>= 1) d += __shfl_xor_sync(0xffffffffu, d, o);
            if (lane == 0) {
                int bid = bid0 + (row >> 5);
                int l   = bid / B_;
                int b   = bid % B_;
                int m   = row & 31;
                bool valid = mask[((size_t)b * N_ + m) * L_ + l] != 0;
                red_s[row] = valid ? (d + ab2[0]) : -INFINITY;
            }
        }
    }
    __syncthreads();

    // ---- Phase 7: masked softmax per group (warps 0 and 1) ----
    if (warp < 2) {
        int bid = bid0 + warp;
        int l   = bid / B_;
        int b   = bid % B_;
        float lg = red_s[warp * 32 + lane];
        float mx = lg;
        #pragma unroll
        for (int o = 16; o; o >>= 1) mx = fmaxf(mx, __shfl_xor_sync(0xffffffffu, mx, o));
        float e = (mx == -INFINITY || lg == -INFINITY) ? 0.f : __expf(lg - mx);
        float s = e;
        #pragma unroll
        for (int o = 16; o; o >>= 1) s += __shfl_xor_sync(0xffffffffu, s, o);
        float a = (s > 0.f) ? (e / s) : 0.f;
        attn_s[warp * 32 + lane] = a;
        out_attn[(size_t)b * L_ * N_ + (size_t)l * N_ + lane] = a;
    }
    __syncthreads();

    // ---- Phase 8: fused[bid,d] = sum_n attn[n]*per_msg[n,d]; each half its group ----
    {
        float facc = 0.f;
        #pragma unroll 8
        for (int n = 0; n < N_; ++n)
            facc += attn_s[half * 32 + n] * vert_s[(half * 32 + n) * D_ + htid];
        out_fused[(size_t)(bid0 + half) * D_ + htid] = facc;
    }
}

extern "C" void kernel_launch(void* const* d_in, const int* in_sizes, int n_in,
                              void* d_out, int out_size) {
    const float* vert  = (const float*)d_in[0];
    const float* horiz = (const float*)d_in[1];
    const int*   mask  = (const int*)d_in[2];
    const float* gw1 = (const float*)d_in[3];
    const float* gb1 = (const float*)d_in[4];
    const float* gw2 = (const float*)d_in[5];
    const float* gb2 = (const float*)d_in[6];
    const float* aw1 = (const float*)d_in[7];
    const float* ab1 = (const float*)d_in[8];
    const float* aw2 = (const float*)d_in[9];
    const float* ab2 = (const float*)d_in[10];

    float* out = (float*)d_out;
    float* out_fused = out;                                   // L*B*D
    float* out_pm    = out + (size_t)L_ * B_ * D_;            // L*B*N*D
    float* out_attn  = out_pm + (size_t)L_ * B_ * N_ * D_;    // B*L*N

    const size_t smem_bytes = (size_t)(M2_ * D_ * 2 + 4 * 4096 + 3 * M2_) * sizeof(float);

    cudaFuncSetAttribute(fused_kernel,
                         cudaFuncAttributeMaxDynamicSharedMemorySize,
                         (int)smem_bytes);

    transpose_weights_kernel<<<(2 * D_ * GH_ + 255) / 256, 256>>>(gw1, aw1);
    fused_kernel<<<L_ * B_ / 2, 512, smem_bytes>>>(
        vert, horiz, mask, gb1, gw2, gb2, ab1, aw2, ab2,
        out_fused, out_pm, out_attn);
}